// round 1
// baseline (speedup 1.0000x reference)
#include <cuda_runtime.h>

#define P_N 200000
#define C_N 50000
#define L_N 8
#define F_N 32
#define DIN 64
#define NSTEPS 5

typedef unsigned long long u64;

// ---------------- device scratch (no allocations allowed) ----------------
__device__ float g_p[(size_t)P_N * F_N];     // path state, sorted order (25.6 MB)
__device__ int   g_order[P_N];               // sorted slot -> original path id
__device__ int   g_idx[(size_t)P_N * L_N];   // channel idx rows, sorted order
__device__ int   g_len[P_N];                 // lengths, sorted order
__device__ float g_agg[(size_t)C_N * F_N];   // segment sums (6.4 MB)
__device__ int   g_cnt[16];                  // bucket counts / running offsets

// ---------------- helpers ----------------
__device__ __forceinline__ u64 ffma2(u64 a, u64 b, u64 c) {
    u64 d;
    asm("fma.rn.f32x2 %0, %1, %2, %3;" : "=l"(d) : "l"(a), "l"(b), "l"(c));
    return d;
}
__device__ __forceinline__ float2 u2f(u64 v) {
    float2 r;
    asm("mov.b64 {%0,%1}, %2;" : "=f"(r.x), "=f"(r.y) : "l"(v));
    return r;
}
__device__ __forceinline__ u64 f2u(float a, float b) {
    u64 r;
    asm("mov.b64 %0, {%1,%2};" : "=l"(r) : "f"(a), "f"(b));
    return r;
}
__device__ __forceinline__ float hsum(u64 v) { float2 f = u2f(v); return f.x + f.y; }

__device__ __forceinline__ float fast_sigmoid(float v) {
    float e;
    asm("ex2.approx.f32 %0, %1;" : "=f"(e) : "f"(v * -1.4426950408889634f));
    float r;
    asm("rcp.approx.f32 %0, %1;" : "=f"(r) : "f"(1.0f + e));
    return r;
}
__device__ __forceinline__ float fast_tanh(float v) {
    // tanh(v) = 1 - 2/(exp(2v)+1)
    float e;
    asm("ex2.approx.f32 %0, %1;" : "=f"(e) : "f"(v * 2.885390081777927f));
    float r;
    asm("rcp.approx.f32 %0, %1;" : "=f"(r) : "f"(1.0f + e));
    return 1.0f - 2.0f * r;
}

__device__ __forceinline__ void red_add_v4(float* p, float4 v) {
    asm volatile("red.global.add.v4.f32 [%0], {%1,%2,%3,%4};"
                 :: "l"(p), "f"(v.x), "f"(v.y), "f"(v.z), "f"(v.w) : "memory");
}

// One GRU sub-step: h (in shared, stride-1 row of 32) updated in place.
// x2: 16 packed f32x2 of the input vector. Weights staged in shared (row-major [96][32]).
__device__ __forceinline__ void gru_sub(float* __restrict__ hrow,
                                        const u64* __restrict__ x2,
                                        const float* __restrict__ sWi,
                                        const float* __restrict__ sWh,
                                        const float* __restrict__ sbi,
                                        const float* __restrict__ sbh)
{
    u64 h2[16];
#pragma unroll
    for (int k = 0; k < 16; k++) h2[k] = f2u(hrow[2 * k], hrow[2 * k + 1]);
    const u64* wi = (const u64*)sWi;
    const u64* wh = (const u64*)sWh;
#pragma unroll 4
    for (int f = 0; f < F_N; f++) {
        const u64* wir = wi + f * 16;
        const u64* wiz = wi + (F_N + f) * 16;
        const u64* win = wi + (2 * F_N + f) * 16;
        const u64* whr = wh + f * 16;
        const u64* whz = wh + (F_N + f) * 16;
        const u64* whn = wh + (2 * F_N + f) * 16;
        u64 air = 0, aiz = 0, ain = 0, ahr = 0, ahz = 0, ahn = 0;
#pragma unroll
        for (int k = 0; k < 16; k++) {
            air = ffma2(x2[k], wir[k], air);
            ahr = ffma2(h2[k], whr[k], ahr);
            aiz = ffma2(x2[k], wiz[k], aiz);
            ahz = ffma2(h2[k], whz[k], ahz);
            ain = ffma2(x2[k], win[k], ain);
            ahn = ffma2(h2[k], whn[k], ahn);
        }
        float r = fast_sigmoid(hsum(air) + sbi[f] + hsum(ahr) + sbh[f]);
        float z = fast_sigmoid(hsum(aiz) + sbi[F_N + f] + hsum(ahz) + sbh[F_N + f]);
        float n = fast_tanh(hsum(ain) + sbi[2 * F_N + f] + r * (hsum(ahn) + sbh[2 * F_N + f]));
        float hold = hrow[f];
        hrow[f] = (1.0f - z) * n + z * hold;
    }
}

// ---------------- sorting (counting sort by length, static across steps) ----------------
__global__ void zero_cnt_kernel() {
    int i = threadIdx.x;
    if (i < 16) g_cnt[i] = 0;
}
__global__ void hist_kernel(const int* __restrict__ plen) {
    int i = blockIdx.x * blockDim.x + threadIdx.x;
    if (i < P_N) {
        int b = plen[i]; b = b < 0 ? 0 : (b > 7 ? 7 : b);
        atomicAdd(&g_cnt[b], 1);
    }
}
__global__ void prefix_kernel() {
    if (threadIdx.x == 0 && blockIdx.x == 0) {
        int acc = 0;
#pragma unroll
        for (int b = 0; b < 8; b++) { int cv = g_cnt[b]; g_cnt[b] = acc; acc += cv; }
    }
}
__global__ void scatter_kernel(const int* __restrict__ plen) {
    int i = blockIdx.x * blockDim.x + threadIdx.x;
    if (i < P_N) {
        int b = plen[i]; b = b < 0 ? 0 : (b > 7 ? 7 : b);
        int pos = atomicAdd(&g_cnt[b], 1);
        g_order[pos] = i;
    }
}

// ---------------- build: gather len/idx into sorted order + init p ----------------
__global__ void __launch_bounds__(128) build_kernel(const int* __restrict__ plen,
                                                    const int* __restrict__ pci,
                                                    const float* __restrict__ praw,
                                                    const float* __restrict__ W,
                                                    const float* __restrict__ b)
{
    __shared__ __align__(16) float sWt[F_N * DIN];  // transposed: [f][d]
    __shared__ float sb[F_N];
    int tid = threadIdx.x;
    for (int i = tid; i < DIN * F_N; i += 128) {
        int d = i >> 5, f = i & 31;
        sWt[f * DIN + d] = W[i];
    }
    if (tid < F_N) sb[tid] = b[tid];
    __syncthreads();
    int s = blockIdx.x * 128 + tid;
    if (s >= P_N) return;
    int path = g_order[s];
    g_len[s] = plen[path];
    const int4* si = (const int4*)(pci + (size_t)path * L_N);
    int4* di = (int4*)(g_idx + (size_t)s * L_N);
    di[0] = si[0]; di[1] = si[1];

    u64 x2[32];
    const ulonglong2* xg = (const ulonglong2*)(praw + (size_t)path * DIN);
#pragma unroll
    for (int q = 0; q < 16; q++) { ulonglong2 v = xg[q]; x2[2 * q] = v.x; x2[2 * q + 1] = v.y; }
    const u64* wt = (const u64*)sWt;
    float4* outp4 = (float4*)(g_p + (size_t)s * F_N);
    for (int f0 = 0; f0 < F_N; f0 += 4) {
        u64 a0 = 0, a1 = 0, a2 = 0, a3 = 0;
        const u64* w0 = wt + (f0 + 0) * 32;
        const u64* w1 = wt + (f0 + 1) * 32;
        const u64* w2 = wt + (f0 + 2) * 32;
        const u64* w3 = wt + (f0 + 3) * 32;
#pragma unroll
        for (int k = 0; k < 32; k++) {
            a0 = ffma2(x2[k], w0[k], a0);
            a1 = ffma2(x2[k], w1[k], a1);
            a2 = ffma2(x2[k], w2[k], a2);
            a3 = ffma2(x2[k], w3[k], a3);
        }
        float4 r;
        r.x = fmaxf(hsum(a0) + sb[f0 + 0], 0.0f);
        r.y = fmaxf(hsum(a1) + sb[f0 + 1], 0.0f);
        r.z = fmaxf(hsum(a2) + sb[f0 + 2], 0.0f);
        r.w = fmaxf(hsum(a3) + sb[f0 + 3], 0.0f);
        outp4[f0 >> 2] = r;
    }
}

// ---------------- init c ----------------
__global__ void __launch_bounds__(128) initc_kernel(const float* __restrict__ craw,
                                                    const float* __restrict__ W,
                                                    const float* __restrict__ b,
                                                    float* __restrict__ c)
{
    __shared__ __align__(16) float sWt[F_N * DIN];
    __shared__ float sb[F_N];
    int tid = threadIdx.x;
    for (int i = tid; i < DIN * F_N; i += 128) {
        int d = i >> 5, f = i & 31;
        sWt[f * DIN + d] = W[i];
    }
    if (tid < F_N) sb[tid] = b[tid];
    __syncthreads();
    int ch = blockIdx.x * 128 + tid;
    if (ch >= C_N) return;
    u64 x2[32];
    const ulonglong2* xg = (const ulonglong2*)(craw + (size_t)ch * DIN);
#pragma unroll
    for (int q = 0; q < 16; q++) { ulonglong2 v = xg[q]; x2[2 * q] = v.x; x2[2 * q + 1] = v.y; }
    const u64* wt = (const u64*)sWt;
    float4* out4 = (float4*)(c + (size_t)ch * F_N);
    for (int f0 = 0; f0 < F_N; f0 += 4) {
        u64 a0 = 0, a1 = 0, a2 = 0, a3 = 0;
        const u64* w0 = wt + (f0 + 0) * 32;
        const u64* w1 = wt + (f0 + 1) * 32;
        const u64* w2 = wt + (f0 + 2) * 32;
        const u64* w3 = wt + (f0 + 3) * 32;
#pragma unroll
        for (int k = 0; k < 32; k++) {
            a0 = ffma2(x2[k], w0[k], a0);
            a1 = ffma2(x2[k], w1[k], a1);
            a2 = ffma2(x2[k], w2[k], a2);
            a3 = ffma2(x2[k], w3[k], a3);
        }
        float4 r;
        r.x = fmaxf(hsum(a0) + sb[f0 + 0], 0.0f);
        r.y = fmaxf(hsum(a1) + sb[f0 + 1], 0.0f);
        r.z = fmaxf(hsum(a2) + sb[f0 + 2], 0.0f);
        r.w = fmaxf(hsum(a3) + sb[f0 + 3], 0.0f);
        out4[f0 >> 2] = r;
    }
}

// ---------------- per-step: masked GRU scan over t, fused segment-sum atomics ----------------
__global__ void __launch_bounds__(128) scan_kernel(const float* __restrict__ c,
                                                   const float* __restrict__ Wi,
                                                   const float* __restrict__ Wh,
                                                   const float* __restrict__ bi,
                                                   const float* __restrict__ bh)
{
    __shared__ __align__(16) float sW[2 * 96 * F_N + 2 * 96];
    __shared__ float sH[128 * 33];
    float* sWi = sW;
    float* sWh = sW + 96 * F_N;
    float* sbi = sW + 2 * 96 * F_N;
    float* sbh = sbi + 96;
    int tid = threadIdx.x;
    for (int i = tid; i < 96 * F_N; i += 128) { sWi[i] = Wi[i]; sWh[i] = Wh[i]; }
    if (tid < 96) { sbi[tid] = bi[tid]; sbh[tid] = bh[tid]; }
    __syncthreads();
    int s = blockIdx.x * 128 + tid;
    if (s >= P_N) return;
    int len = g_len[s];
    float* hrow = sH + tid * 33;
    {
        const float4* gp = (const float4*)(g_p + (size_t)s * F_N);
#pragma unroll
        for (int q = 0; q < 8; q++) {
            float4 v = gp[q];
            hrow[4 * q] = v.x; hrow[4 * q + 1] = v.y; hrow[4 * q + 2] = v.z; hrow[4 * q + 3] = v.w;
        }
    }
    const int* idxrow = g_idx + (size_t)s * L_N;
#pragma unroll 1
    for (int t = 0; t < L_N; t++) {
        if (t > len) break;
        int ch = __ldg(idxrow + t);
        u64 x2[16];
        const ulonglong2* xg = (const ulonglong2*)(c + (size_t)ch * F_N);
#pragma unroll
        for (int q = 0; q < 8; q++) { ulonglong2 v = xg[q]; x2[2 * q] = v.x; x2[2 * q + 1] = v.y; }
        gru_sub(hrow, x2, sWi, sWh, sbi, sbh);
    }
    float4 hv[8];
#pragma unroll
    for (int q = 0; q < 8; q++)
        hv[q] = make_float4(hrow[4 * q], hrow[4 * q + 1], hrow[4 * q + 2], hrow[4 * q + 3]);
    {
        float4* gp = (float4*)(g_p + (size_t)s * F_N);
#pragma unroll
        for (int q = 0; q < 8; q++) gp[q] = hv[q];
    }
#pragma unroll
    for (int t = 0; t < L_N; t++) {
        if (t <= len) {
            int ch = __ldg(idxrow + t);
            float* base = g_agg + (size_t)ch * F_N;
#pragma unroll
            for (int q = 0; q < 8; q++) red_add_v4(base + 4 * q, hv[q]);
        }
    }
}

// ---------------- per-step: channel GRU update ----------------
__global__ void __launch_bounds__(128) gru2_kernel(float* __restrict__ c,
                                                   const float* __restrict__ Wi,
                                                   const float* __restrict__ Wh,
                                                   const float* __restrict__ bi,
                                                   const float* __restrict__ bh)
{
    __shared__ __align__(16) float sW[2 * 96 * F_N + 2 * 96];
    __shared__ float sH[128 * 33];
    float* sWi = sW;
    float* sWh = sW + 96 * F_N;
    float* sbi = sW + 2 * 96 * F_N;
    float* sbh = sbi + 96;
    int tid = threadIdx.x;
    for (int i = tid; i < 96 * F_N; i += 128) { sWi[i] = Wi[i]; sWh[i] = Wh[i]; }
    if (tid < 96) { sbi[tid] = bi[tid]; sbh[tid] = bh[tid]; }
    __syncthreads();
    int ch = blockIdx.x * 128 + tid;
    if (ch >= C_N) return;
    float* hrow = sH + tid * 33;
    {
        const float4* cp = (const float4*)(c + (size_t)ch * F_N);
#pragma unroll
        for (int q = 0; q < 8; q++) {
            float4 v = cp[q];
            hrow[4 * q] = v.x; hrow[4 * q + 1] = v.y; hrow[4 * q + 2] = v.z; hrow[4 * q + 3] = v.w;
        }
    }
    u64 x2[16];
    const ulonglong2* xg = (const ulonglong2*)(g_agg + (size_t)ch * F_N);
#pragma unroll
    for (int q = 0; q < 8; q++) { ulonglong2 v = xg[q]; x2[2 * q] = v.x; x2[2 * q + 1] = v.y; }
    gru_sub(hrow, x2, sWi, sWh, sbi, sbh);
    float4* cp = (float4*)(c + (size_t)ch * F_N);
#pragma unroll
    for (int q = 0; q < 8; q++)
        cp[q] = make_float4(hrow[4 * q], hrow[4 * q + 1], hrow[4 * q + 2], hrow[4 * q + 3]);
}

// ---------------- final scatter of p to original order ----------------
__global__ void __launch_bounds__(128) scatterp_kernel(float* __restrict__ outp) {
    int s = blockIdx.x * 128 + threadIdx.x;
    if (s >= P_N) return;
    int path = g_order[s];
    const float4* src = (const float4*)(g_p + (size_t)s * F_N);
    float4* dst = (float4*)(outp + (size_t)path * F_N);
#pragma unroll
    for (int q = 0; q < 8; q++) dst[q] = src[q];
}

// ---------------- launch ----------------
extern "C" void kernel_launch(void* const* d_in, const int* in_sizes, int n_in,
                              void* d_out, int out_size)
{
    const float* path_raw    = (const float*)d_in[0];
    const float* channel_raw = (const float*)d_in[1];
    const int*   pci         = (const int*)d_in[2];
    const int*   plen        = (const int*)d_in[3];
    // d_in[4] = num_steps (constant 5 in this dataset)
    const float* Wp  = (const float*)d_in[5];
    const float* bp  = (const float*)d_in[6];
    const float* Wc  = (const float*)d_in[7];
    const float* bc  = (const float*)d_in[8];
    const float* Wi1 = (const float*)d_in[9];
    const float* Wh1 = (const float*)d_in[10];
    const float* bi1 = (const float*)d_in[11];
    const float* bh1 = (const float*)d_in[12];
    const float* Wi2 = (const float*)d_in[13];
    const float* Wh2 = (const float*)d_in[14];
    const float* bi2 = (const float*)d_in[15];
    const float* bh2 = (const float*)d_in[16];

    float* outp = (float*)d_out;
    float* c    = outp + (size_t)P_N * F_N;

    void* aggPtr = nullptr;
    cudaGetSymbolAddress(&aggPtr, g_agg);

    int gridP = (P_N + 127) / 128;
    int gridC = (C_N + 127) / 128;

    zero_cnt_kernel<<<1, 32>>>();
    hist_kernel<<<gridP, 128>>>(plen);
    prefix_kernel<<<1, 32>>>();
    scatter_kernel<<<gridP, 128>>>(plen);
    build_kernel<<<gridP, 128>>>(plen, pci, path_raw, Wp, bp);
    initc_kernel<<<gridC, 128>>>(channel_raw, Wc, bc, c);

    for (int st = 0; st < NSTEPS; st++) {
        cudaMemsetAsync(aggPtr, 0, sizeof(float) * (size_t)C_N * F_N, 0);
        scan_kernel<<<gridP, 128>>>(c, Wi1, Wh1, bi1, bh1);
        gru2_kernel<<<gridC, 128>>>(c, Wi2, Wh2, bi2, bh2);
    }
    scatterp_kernel<<<gridP, 128>>>(outp);
}

// round 2
// speedup vs baseline: 1.1719x; 1.1719x over previous
#include <cuda_runtime.h>

#define P_N 200000
#define C_N 50000
#define L_N 8
#define F_N 32
#define DIN 64
#define NSTEPS 5

typedef unsigned long long u64;

// ---------------- device scratch (no allocations allowed) ----------------
__device__ float g_p[(size_t)P_N * F_N];      // path state, sorted order
__device__ int   g_order[P_N];                // sorted slot -> original path id
__device__ int   g_idx[(size_t)P_N * L_N];    // channel idx rows, sorted order
__device__ int   g_len[P_N];                  // lengths, sorted order
__device__ float g_agg[(size_t)C_N * F_N];    // segment sums
__device__ float g_table[(size_t)C_N * 96];   // precomputed gi table (19.2 MB)
__device__ int   g_cnt[16];

// ---------------- helpers ----------------
__device__ __forceinline__ u64 ffma2(u64 a, u64 b, u64 c) {
    u64 d;
    asm("fma.rn.f32x2 %0, %1, %2, %3;" : "=l"(d) : "l"(a), "l"(b), "l"(c));
    return d;
}
__device__ __forceinline__ float2 u2f(u64 v) {
    float2 r;
    asm("mov.b64 {%0,%1}, %2;" : "=f"(r.x), "=f"(r.y) : "l"(v));
    return r;
}
__device__ __forceinline__ u64 f2u(float a, float b) {
    u64 r;
    asm("mov.b64 %0, {%1,%2};" : "=l"(r) : "f"(a), "f"(b));
    return r;
}
__device__ __forceinline__ float hsum(u64 v) { float2 f = u2f(v); return f.x + f.y; }

__device__ __forceinline__ float fast_sigmoid(float v) {
    float e;
    asm("ex2.approx.f32 %0, %1;" : "=f"(e) : "f"(v * -1.4426950408889634f));
    float r;
    asm("rcp.approx.f32 %0, %1;" : "=f"(r) : "f"(1.0f + e));
    return r;
}
__device__ __forceinline__ float fast_tanh(float v) {
    float e;
    asm("ex2.approx.f32 %0, %1;" : "=f"(e) : "f"(v * 2.885390081777927f));
    float r;
    asm("rcp.approx.f32 %0, %1;" : "=f"(r) : "f"(1.0f + e));
    return 1.0f - 2.0f * r;
}
__device__ __forceinline__ void red_add_v4(float* p, float4 v) {
    asm volatile("red.global.add.v4.f32 [%0], {%1,%2,%3,%4};"
                 :: "l"(p), "f"(v.x), "f"(v.y), "f"(v.z), "f"(v.w) : "memory");
}

// Column-major 32->96 matvec. h: 32 scalar regs. sWT: [k][out] = W[out][k], warp-uniform
// shared. Produces 48 packed f32x2 accumulators (lane pair = outputs 2p, 2p+1).
__device__ __forceinline__ void matvec96_col(const float* __restrict__ h,
                                             const float* __restrict__ sWT,
                                             u64* __restrict__ acc)
{
#pragma unroll
    for (int p = 0; p < 48; p++) acc[p] = 0ull;
#pragma unroll 8
    for (int k = 0; k < 32; k++) {
        u64 d = f2u(h[k], h[k]);
        const u64* w = (const u64*)(sWT + k * 96);
#pragma unroll
        for (int p = 0; p < 48; p++) acc[p] = ffma2(d, w[p], acc[p]);
    }
}

// GRU epilogue: tg = 24 float4 of the gi row [r(32) z(32) n(32)], bh_r/bh_z folded
// into the table; sbhn holds bh_n (32 floats). h updated in place.
__device__ __forceinline__ void gru_epilogue(float* __restrict__ h,
                                             const float4* __restrict__ tg,
                                             const u64* __restrict__ acc,
                                             const float* __restrict__ sbhn)
{
#pragma unroll
    for (int g = 0; g < 4; g++) {
        float4 gr0 = tg[2 * g];      float4 gr1 = tg[2 * g + 1];
        float4 gz0 = tg[8 + 2 * g];  float4 gz1 = tg[8 + 2 * g + 1];
        float4 gn0 = tg[16 + 2 * g]; float4 gn1 = tg[16 + 2 * g + 1];
        float gr[8] = {gr0.x, gr0.y, gr0.z, gr0.w, gr1.x, gr1.y, gr1.z, gr1.w};
        float gz[8] = {gz0.x, gz0.y, gz0.z, gz0.w, gz1.x, gz1.y, gz1.z, gz1.w};
        float gn[8] = {gn0.x, gn0.y, gn0.z, gn0.w, gn1.x, gn1.y, gn1.z, gn1.w};
#pragma unroll
        for (int j = 0; j < 8; j++) {
            int f = 8 * g + j;
            int p = f >> 1;
            float2 ar = u2f(acc[p]);
            float2 az = u2f(acc[16 + p]);
            float2 an = u2f(acc[32 + p]);
            float vr = (f & 1) ? ar.y : ar.x;
            float vz = (f & 1) ? az.y : az.x;
            float vn = (f & 1) ? an.y : an.x;
            float r = fast_sigmoid(gr[j] + vr);
            float z = fast_sigmoid(gz[j] + vz);
            float n = fast_tanh(gn[j] + r * (vn + sbhn[f]));
            h[f] = n + z * (h[f] - n);
        }
    }
}

// ---------------- sorting (counting sort, DESCENDING length) ----------------
__global__ void zero_cnt_kernel() { if (threadIdx.x < 16) g_cnt[threadIdx.x] = 0; }

__global__ void hist_kernel(const int* __restrict__ plen) {
    int i = blockIdx.x * blockDim.x + threadIdx.x;
    if (i < P_N) {
        int b = plen[i]; b = b < 0 ? 0 : (b > 7 ? 7 : b);
        atomicAdd(&g_cnt[b], 1);
    }
}
__global__ void prefix_kernel() {
    if (threadIdx.x == 0 && blockIdx.x == 0) {
        int acc = 0;
#pragma unroll
        for (int b = 7; b >= 0; b--) { int cv = g_cnt[b]; g_cnt[b] = acc; acc += cv; }
    }
}
__global__ void scatter_kernel(const int* __restrict__ plen) {
    int i = blockIdx.x * blockDim.x + threadIdx.x;
    if (i < P_N) {
        int b = plen[i]; b = b < 0 ? 0 : (b > 7 ? 7 : b);
        int pos = atomicAdd(&g_cnt[b], 1);
        g_order[pos] = i;
    }
}

// ---------------- build: gather len/idx into sorted order + init p ----------------
__global__ void __launch_bounds__(128) build_kernel(const int* __restrict__ plen,
                                                    const int* __restrict__ pci,
                                                    const float* __restrict__ praw,
                                                    const float* __restrict__ W,
                                                    const float* __restrict__ b)
{
    __shared__ __align__(16) float sWt[F_N * DIN];  // [f][d]
    __shared__ float sb[F_N];
    int tid = threadIdx.x;
    for (int i = tid; i < DIN * F_N; i += 128) {
        int d = i >> 5, f = i & 31;
        sWt[f * DIN + d] = W[i];
    }
    if (tid < F_N) sb[tid] = b[tid];
    __syncthreads();
    int s = blockIdx.x * 128 + tid;
    if (s >= P_N) return;
    int path = g_order[s];
    g_len[s] = plen[path];
    const int4* si = (const int4*)(pci + (size_t)path * L_N);
    int4* di = (int4*)(g_idx + (size_t)s * L_N);
    di[0] = si[0]; di[1] = si[1];

    u64 x2[32];
    const ulonglong2* xg = (const ulonglong2*)(praw + (size_t)path * DIN);
#pragma unroll
    for (int q = 0; q < 16; q++) { ulonglong2 v = xg[q]; x2[2 * q] = v.x; x2[2 * q + 1] = v.y; }
    const u64* wt = (const u64*)sWt;
    float4* outp4 = (float4*)(g_p + (size_t)s * F_N);
    for (int f0 = 0; f0 < F_N; f0 += 4) {
        u64 a0 = 0, a1 = 0, a2 = 0, a3 = 0;
        const u64* w0 = wt + (f0 + 0) * 32;
        const u64* w1 = wt + (f0 + 1) * 32;
        const u64* w2 = wt + (f0 + 2) * 32;
        const u64* w3 = wt + (f0 + 3) * 32;
#pragma unroll
        for (int k = 0; k < 32; k++) {
            a0 = ffma2(x2[k], w0[k], a0);
            a1 = ffma2(x2[k], w1[k], a1);
            a2 = ffma2(x2[k], w2[k], a2);
            a3 = ffma2(x2[k], w3[k], a3);
        }
        float4 r;
        r.x = fmaxf(hsum(a0) + sb[f0 + 0], 0.0f);
        r.y = fmaxf(hsum(a1) + sb[f0 + 1], 0.0f);
        r.z = fmaxf(hsum(a2) + sb[f0 + 2], 0.0f);
        r.w = fmaxf(hsum(a3) + sb[f0 + 3], 0.0f);
        outp4[f0 >> 2] = r;
    }
}

// ---------------- init c ----------------
__global__ void __launch_bounds__(128) initc_kernel(const float* __restrict__ craw,
                                                    const float* __restrict__ W,
                                                    const float* __restrict__ b,
                                                    float* __restrict__ c)
{
    __shared__ __align__(16) float sWt[F_N * DIN];
    __shared__ float sb[F_N];
    int tid = threadIdx.x;
    for (int i = tid; i < DIN * F_N; i += 128) {
        int d = i >> 5, f = i & 31;
        sWt[f * DIN + d] = W[i];
    }
    if (tid < F_N) sb[tid] = b[tid];
    __syncthreads();
    int ch = blockIdx.x * 128 + tid;
    if (ch >= C_N) return;
    u64 x2[32];
    const ulonglong2* xg = (const ulonglong2*)(craw + (size_t)ch * DIN);
#pragma unroll
    for (int q = 0; q < 16; q++) { ulonglong2 v = xg[q]; x2[2 * q] = v.x; x2[2 * q + 1] = v.y; }
    const u64* wt = (const u64*)sWt;
    float4* out4 = (float4*)(c + (size_t)ch * F_N);
    for (int f0 = 0; f0 < F_N; f0 += 4) {
        u64 a0 = 0, a1 = 0, a2 = 0, a3 = 0;
        const u64* w0 = wt + (f0 + 0) * 32;
        const u64* w1 = wt + (f0 + 1) * 32;
        const u64* w2 = wt + (f0 + 2) * 32;
        const u64* w3 = wt + (f0 + 3) * 32;
#pragma unroll
        for (int k = 0; k < 32; k++) {
            a0 = ffma2(x2[k], w0[k], a0);
            a1 = ffma2(x2[k], w1[k], a1);
            a2 = ffma2(x2[k], w2[k], a2);
            a3 = ffma2(x2[k], w3[k], a3);
        }
        float4 r;
        r.x = fmaxf(hsum(a0) + sb[f0 + 0], 0.0f);
        r.y = fmaxf(hsum(a1) + sb[f0 + 1], 0.0f);
        r.z = fmaxf(hsum(a2) + sb[f0 + 2], 0.0f);
        r.w = fmaxf(hsum(a3) + sb[f0 + 3], 0.0f);
        out4[f0 >> 2] = r;
    }
}

// ---------------- gi table: T[row] = x[row]@Wi^T + bi (+bh folded into r,z) ----------------
__global__ void __launch_bounds__(128) gi_kernel(const float* __restrict__ x, int nrows,
                                                 const float* __restrict__ Wi,
                                                 const float* __restrict__ bi,
                                                 const float* __restrict__ bh)
{
    __shared__ __align__(16) float sWT[32 * 96];
    __shared__ float sb[96];
    int tid = threadIdx.x;
    for (int i = tid; i < 96 * 32; i += 128) {
        int out = i >> 5, k = i & 31;
        sWT[k * 96 + out] = Wi[i];
    }
    if (tid < 96) sb[tid] = bi[tid] + (tid < 64 ? bh[tid] : 0.0f);
    __syncthreads();
    int row = blockIdx.x * 128 + tid;
    if (row >= nrows) return;
    float h[32];
    const float4* xr = (const float4*)(x + (size_t)row * 32);
#pragma unroll
    for (int q = 0; q < 8; q++) {
        float4 v = xr[q];
        h[4 * q] = v.x; h[4 * q + 1] = v.y; h[4 * q + 2] = v.z; h[4 * q + 3] = v.w;
    }
    u64 acc[48];
    matvec96_col(h, sWT, acc);
    float4* t4 = (float4*)(g_table + (size_t)row * 96);
#pragma unroll
    for (int p = 0; p < 24; p++) {
        float2 a = u2f(acc[2 * p]);
        float2 b = u2f(acc[2 * p + 1]);
        t4[p] = make_float4(a.x + sb[4 * p], a.y + sb[4 * p + 1],
                            b.x + sb[4 * p + 2], b.y + sb[4 * p + 3]);
    }
}

// ---------------- per-step scan: h-matvec only, gi gathered from table ----------------
__global__ void __launch_bounds__(128) scan_kernel(const float* __restrict__ Wh,
                                                   const float* __restrict__ bh)
{
    __shared__ __align__(16) float sWT[32 * 96];
    __shared__ float sbhn[32];
    int tid = threadIdx.x;
    for (int i = tid; i < 96 * 32; i += 128) {
        int out = i >> 5, k = i & 31;
        sWT[k * 96 + out] = Wh[i];
    }
    if (tid < 32) sbhn[tid] = bh[64 + tid];
    __syncthreads();
    int s = blockIdx.x * 128 + tid;
    if (s >= P_N) return;
    int len = g_len[s];
    float h[32];
    {
        const float4* gp = (const float4*)(g_p + (size_t)s * F_N);
#pragma unroll
        for (int q = 0; q < 8; q++) {
            float4 v = gp[q];
            h[4 * q] = v.x; h[4 * q + 1] = v.y; h[4 * q + 2] = v.z; h[4 * q + 3] = v.w;
        }
    }
    const int* idxrow = g_idx + (size_t)s * L_N;
#pragma unroll 1
    for (int t = 0; t < L_N; t++) {
        if (t > len) break;
        int ch = __ldg(idxrow + t);
        const float4* tg = (const float4*)(g_table + (size_t)ch * 96);
        u64 acc[48];
        matvec96_col(h, sWT, acc);
        gru_epilogue(h, tg, acc, sbhn);
    }
    float4 hv[8];
#pragma unroll
    for (int q = 0; q < 8; q++)
        hv[q] = make_float4(h[4 * q], h[4 * q + 1], h[4 * q + 2], h[4 * q + 3]);
    {
        float4* gp = (float4*)(g_p + (size_t)s * F_N);
#pragma unroll
        for (int q = 0; q < 8; q++) gp[q] = hv[q];
    }
#pragma unroll 1
    for (int t = 0; t < L_N; t++) {
        if (t > len) break;
        int ch = __ldg(idxrow + t);
        float* base = g_agg + (size_t)ch * F_N;
#pragma unroll
        for (int q = 0; q < 8; q++) red_add_v4(base + 4 * q, hv[q]);
    }
}

// ---------------- per-step: channel GRU (gi from table on agg, coalesced) ----------------
__global__ void __launch_bounds__(128) gru2_kernel(float* __restrict__ c,
                                                   const float* __restrict__ Wh,
                                                   const float* __restrict__ bh)
{
    __shared__ __align__(16) float sWT[32 * 96];
    __shared__ float sbhn[32];
    int tid = threadIdx.x;
    for (int i = tid; i < 96 * 32; i += 128) {
        int out = i >> 5, k = i & 31;
        sWT[k * 96 + out] = Wh[i];
    }
    if (tid < 32) sbhn[tid] = bh[64 + tid];
    __syncthreads();
    int ch = blockIdx.x * 128 + tid;
    if (ch >= C_N) return;
    float h[32];
    {
        const float4* cp = (const float4*)(c + (size_t)ch * F_N);
#pragma unroll
        for (int q = 0; q < 8; q++) {
            float4 v = cp[q];
            h[4 * q] = v.x; h[4 * q + 1] = v.y; h[4 * q + 2] = v.z; h[4 * q + 3] = v.w;
        }
    }
    const float4* tg = (const float4*)(g_table + (size_t)ch * 96);
    u64 acc[48];
    matvec96_col(h, sWT, acc);
    gru_epilogue(h, tg, acc, sbhn);
    float4* cp = (float4*)(c + (size_t)ch * F_N);
#pragma unroll
    for (int q = 0; q < 8; q++)
        cp[q] = make_float4(h[4 * q], h[4 * q + 1], h[4 * q + 2], h[4 * q + 3]);
}

// ---------------- final scatter of p to original order ----------------
__global__ void __launch_bounds__(128) scatterp_kernel(float* __restrict__ outp) {
    int s = blockIdx.x * 128 + threadIdx.x;
    if (s >= P_N) return;
    int path = g_order[s];
    const float4* src = (const float4*)(g_p + (size_t)s * F_N);
    float4* dst = (float4*)(outp + (size_t)path * F_N);
#pragma unroll
    for (int q = 0; q < 8; q++) dst[q] = src[q];
}

// ---------------- launch ----------------
extern "C" void kernel_launch(void* const* d_in, const int* in_sizes, int n_in,
                              void* d_out, int out_size)
{
    const float* path_raw    = (const float*)d_in[0];
    const float* channel_raw = (const float*)d_in[1];
    const int*   pci         = (const int*)d_in[2];
    const int*   plen        = (const int*)d_in[3];
    // d_in[4] = num_steps (constant 5 in this dataset)
    const float* Wp  = (const float*)d_in[5];
    const float* bp  = (const float*)d_in[6];
    const float* Wc  = (const float*)d_in[7];
    const float* bc  = (const float*)d_in[8];
    const float* Wi1 = (const float*)d_in[9];
    const float* Wh1 = (const float*)d_in[10];
    const float* bi1 = (const float*)d_in[11];
    const float* bh1 = (const float*)d_in[12];
    const float* Wi2 = (const float*)d_in[13];
    const float* Wh2 = (const float*)d_in[14];
    const float* bi2 = (const float*)d_in[15];
    const float* bh2 = (const float*)d_in[16];

    float* outp = (float*)d_out;
    float* c    = outp + (size_t)P_N * F_N;

    void* aggPtr = nullptr;
    cudaGetSymbolAddress(&aggPtr, g_agg);
    float* aggF = (float*)aggPtr;

    int gridP = (P_N + 127) / 128;
    int gridC = (C_N + 127) / 128;

    zero_cnt_kernel<<<1, 32>>>();
    hist_kernel<<<gridP, 128>>>(plen);
    prefix_kernel<<<1, 32>>>();
    scatter_kernel<<<gridP, 128>>>(plen);
    build_kernel<<<gridP, 128>>>(plen, pci, path_raw, Wp, bp);
    initc_kernel<<<gridC, 128>>>(channel_raw, Wc, bc, c);

    for (int st = 0; st < NSTEPS; st++) {
        cudaMemsetAsync(aggPtr, 0, sizeof(float) * (size_t)C_N * F_N, 0);
        gi_kernel<<<gridC, 128>>>(c, C_N, Wi1, bi1, bh1);       // T = c@Wi1^T (+biases)
        scan_kernel<<<gridP, 128>>>(Wh1, bh1);
        gi_kernel<<<gridC, 128>>>(aggF, C_N, Wi2, bi2, bh2);    // T = agg@Wi2^T (+biases)
        gru2_kernel<<<gridC, 128>>>(c, Wh2, bh2);
    }
    scatterp_kernel<<<gridP, 128>>>(outp);
}

// round 3
// speedup vs baseline: 1.3828x; 1.1799x over previous
#include <cuda_runtime.h>

#define P_N 200000
#define C_N 50000
#define L_N 8
#define F_N 32
#define DIN 64
#define NSTEPS 5

#define TILE_P 128
#define SCAN_THREADS 256
#define PSTR 130   // u64 stride of shh rows (16B aligned, staggers banks)

typedef unsigned long long u64;

// ---------------- device scratch ----------------
__device__ float g_p[(size_t)P_N * F_N];
__device__ int   g_order[P_N];
__device__ int   g_idx[(size_t)P_N * L_N];
__device__ int   g_len[P_N];
__device__ float g_agg[(size_t)C_N * F_N];
__device__ float g_table[(size_t)C_N * 96];
__device__ int   g_cnt[16];

// ---------------- helpers ----------------
__device__ __forceinline__ u64 ffma2(u64 a, u64 b, u64 c) {
    u64 d;
    asm("fma.rn.f32x2 %0, %1, %2, %3;" : "=l"(d) : "l"(a), "l"(b), "l"(c));
    return d;
}
__device__ __forceinline__ float2 u2f(u64 v) {
    float2 r;
    asm("mov.b64 {%0,%1}, %2;" : "=f"(r.x), "=f"(r.y) : "l"(v));
    return r;
}
__device__ __forceinline__ u64 f2u(float a, float b) {
    u64 r;
    asm("mov.b64 %0, {%1,%2};" : "=l"(r) : "f"(a), "f"(b));
    return r;
}
__device__ __forceinline__ float hsum(u64 v) { float2 f = u2f(v); return f.x + f.y; }

__device__ __forceinline__ float tanh_ap(float x) {
    float y;
    asm("tanh.approx.f32 %0, %1;" : "=f"(y) : "f"(x));
    return y;
}
__device__ __forceinline__ float fast_sigmoid(float v) {
    return fmaf(0.5f, tanh_ap(0.5f * v), 0.5f);
}
__device__ __forceinline__ float fast_tanh(float v) { return tanh_ap(v); }

__device__ __forceinline__ void red_add_v4(float* p, float4 v) {
    asm volatile("red.global.add.v4.f32 [%0], {%1,%2,%3,%4};"
                 :: "l"(p), "f"(v.x), "f"(v.y), "f"(v.z), "f"(v.w) : "memory");
}
__device__ __forceinline__ u64 ldg64(const u64* p) {
    u64 v;
    asm("ld.global.nc.b64 %0, [%1];" : "=l"(v) : "l"(p));
    return v;
}

// Column-major 32->96 matvec (per-thread row). v2.b64 weight loads.
__device__ __forceinline__ void matvec96_col(const float* __restrict__ h,
                                             const float* __restrict__ sWT,
                                             u64* __restrict__ acc)
{
#pragma unroll
    for (int p = 0; p < 48; p++) acc[p] = 0ull;
#pragma unroll 8
    for (int k = 0; k < 32; k++) {
        u64 d = f2u(h[k], h[k]);
        const ulonglong2* w = (const ulonglong2*)(sWT + k * 96);
#pragma unroll
        for (int p = 0; p < 24; p++) {
            ulonglong2 wv = w[p];
            acc[2 * p]     = ffma2(d, wv.x, acc[2 * p]);
            acc[2 * p + 1] = ffma2(d, wv.y, acc[2 * p + 1]);
        }
    }
}

// GRU epilogue for per-thread-row kernels (gru2).
__device__ __forceinline__ void gru_epilogue(float* __restrict__ h,
                                             const float4* __restrict__ tg,
                                             const u64* __restrict__ acc,
                                             const float* __restrict__ sbhn)
{
#pragma unroll
    for (int g = 0; g < 4; g++) {
        float4 gr0 = tg[2 * g];      float4 gr1 = tg[2 * g + 1];
        float4 gz0 = tg[8 + 2 * g];  float4 gz1 = tg[8 + 2 * g + 1];
        float4 gn0 = tg[16 + 2 * g]; float4 gn1 = tg[16 + 2 * g + 1];
        float gr[8] = {gr0.x, gr0.y, gr0.z, gr0.w, gr1.x, gr1.y, gr1.z, gr1.w};
        float gz[8] = {gz0.x, gz0.y, gz0.z, gz0.w, gz1.x, gz1.y, gz1.z, gz1.w};
        float gn[8] = {gn0.x, gn0.y, gn0.z, gn0.w, gn1.x, gn1.y, gn1.z, gn1.w};
#pragma unroll
        for (int j = 0; j < 8; j++) {
            int f = 8 * g + j;
            int p = f >> 1;
            float2 ar = u2f(acc[p]);
            float2 az = u2f(acc[16 + p]);
            float2 an = u2f(acc[32 + p]);
            float vr = (f & 1) ? ar.y : ar.x;
            float vz = (f & 1) ? az.y : az.x;
            float vn = (f & 1) ? an.y : an.x;
            float r = fast_sigmoid(gr[j] + vr);
            float z = fast_sigmoid(gz[j] + vz);
            float n = fast_tanh(gn[j] + r * (vn + sbhn[f]));
            h[f] = n + z * (h[f] - n);
        }
    }
}

// ---------------- sorting (counting sort, DESCENDING length) ----------------
__global__ void zero_cnt_kernel() { if (threadIdx.x < 16) g_cnt[threadIdx.x] = 0; }

__global__ void hist_kernel(const int* __restrict__ plen) {
    int i = blockIdx.x * blockDim.x + threadIdx.x;
    if (i < P_N) {
        int b = plen[i]; b = b < 0 ? 0 : (b > 7 ? 7 : b);
        atomicAdd(&g_cnt[b], 1);
    }
}
__global__ void prefix_kernel() {
    if (threadIdx.x == 0 && blockIdx.x == 0) {
        int acc = 0;
#pragma unroll
        for (int b = 7; b >= 0; b--) { int cv = g_cnt[b]; g_cnt[b] = acc; acc += cv; }
    }
}
__global__ void scatter_kernel(const int* __restrict__ plen) {
    int i = blockIdx.x * blockDim.x + threadIdx.x;
    if (i < P_N) {
        int b = plen[i]; b = b < 0 ? 0 : (b > 7 ? 7 : b);
        int pos = atomicAdd(&g_cnt[b], 1);
        g_order[pos] = i;
    }
}

// ---------------- build: gather len/idx into sorted order + init p ----------------
__global__ void __launch_bounds__(128) build_kernel(const int* __restrict__ plen,
                                                    const int* __restrict__ pci,
                                                    const float* __restrict__ praw,
                                                    const float* __restrict__ W,
                                                    const float* __restrict__ b)
{
    __shared__ __align__(16) float sWt[F_N * DIN];
    __shared__ float sb[F_N];
    int tid = threadIdx.x;
    for (int i = tid; i < DIN * F_N; i += 128) {
        int d = i >> 5, f = i & 31;
        sWt[f * DIN + d] = W[i];
    }
    if (tid < F_N) sb[tid] = b[tid];
    __syncthreads();
    int s = blockIdx.x * 128 + tid;
    if (s >= P_N) return;
    int path = g_order[s];
    g_len[s] = plen[path];
    const int4* si = (const int4*)(pci + (size_t)path * L_N);
    int4* di = (int4*)(g_idx + (size_t)s * L_N);
    di[0] = si[0]; di[1] = si[1];

    u64 x2[32];
    const ulonglong2* xg = (const ulonglong2*)(praw + (size_t)path * DIN);
#pragma unroll
    for (int q = 0; q < 16; q++) { ulonglong2 v = xg[q]; x2[2 * q] = v.x; x2[2 * q + 1] = v.y; }
    const u64* wt = (const u64*)sWt;
    float4* outp4 = (float4*)(g_p + (size_t)s * F_N);
    for (int f0 = 0; f0 < F_N; f0 += 4) {
        u64 a0 = 0, a1 = 0, a2 = 0, a3 = 0;
        const u64* w0 = wt + (f0 + 0) * 32;
        const u64* w1 = wt + (f0 + 1) * 32;
        const u64* w2 = wt + (f0 + 2) * 32;
        const u64* w3 = wt + (f0 + 3) * 32;
#pragma unroll
        for (int k = 0; k < 32; k++) {
            a0 = ffma2(x2[k], w0[k], a0);
            a1 = ffma2(x2[k], w1[k], a1);
            a2 = ffma2(x2[k], w2[k], a2);
            a3 = ffma2(x2[k], w3[k], a3);
        }
        float4 r;
        r.x = fmaxf(hsum(a0) + sb[f0 + 0], 0.0f);
        r.y = fmaxf(hsum(a1) + sb[f0 + 1], 0.0f);
        r.z = fmaxf(hsum(a2) + sb[f0 + 2], 0.0f);
        r.w = fmaxf(hsum(a3) + sb[f0 + 3], 0.0f);
        outp4[f0 >> 2] = r;
    }
}

// ---------------- init c ----------------
__global__ void __launch_bounds__(128) initc_kernel(const float* __restrict__ craw,
                                                    const float* __restrict__ W,
                                                    const float* __restrict__ b,
                                                    float* __restrict__ c)
{
    __shared__ __align__(16) float sWt[F_N * DIN];
    __shared__ float sb[F_N];
    int tid = threadIdx.x;
    for (int i = tid; i < DIN * F_N; i += 128) {
        int d = i >> 5, f = i & 31;
        sWt[f * DIN + d] = W[i];
    }
    if (tid < F_N) sb[tid] = b[tid];
    __syncthreads();
    int ch = blockIdx.x * 128 + tid;
    if (ch >= C_N) return;
    u64 x2[32];
    const ulonglong2* xg = (const ulonglong2*)(craw + (size_t)ch * DIN);
#pragma unroll
    for (int q = 0; q < 16; q++) { ulonglong2 v = xg[q]; x2[2 * q] = v.x; x2[2 * q + 1] = v.y; }
    const u64* wt = (const u64*)sWt;
    float4* out4 = (float4*)(c + (size_t)ch * F_N);
    for (int f0 = 0; f0 < F_N; f0 += 4) {
        u64 a0 = 0, a1 = 0, a2 = 0, a3 = 0;
        const u64* w0 = wt + (f0 + 0) * 32;
        const u64* w1 = wt + (f0 + 1) * 32;
        const u64* w2 = wt + (f0 + 2) * 32;
        const u64* w3 = wt + (f0 + 3) * 32;
#pragma unroll
        for (int k = 0; k < 32; k++) {
            a0 = ffma2(x2[k], w0[k], a0);
            a1 = ffma2(x2[k], w1[k], a1);
            a2 = ffma2(x2[k], w2[k], a2);
            a3 = ffma2(x2[k], w3[k], a3);
        }
        float4 r;
        r.x = fmaxf(hsum(a0) + sb[f0 + 0], 0.0f);
        r.y = fmaxf(hsum(a1) + sb[f0 + 1], 0.0f);
        r.z = fmaxf(hsum(a2) + sb[f0 + 2], 0.0f);
        r.w = fmaxf(hsum(a3) + sb[f0 + 3], 0.0f);
        out4[f0 >> 2] = r;
    }
}

// ---------------- gi table: T[row] = x[row]@Wi^T + bi (+bh folded into r,z) ----------------
__global__ void __launch_bounds__(128) gi_kernel(const float* __restrict__ x, int nrows,
                                                 const float* __restrict__ Wi,
                                                 const float* __restrict__ bi,
                                                 const float* __restrict__ bh)
{
    __shared__ __align__(16) float sWT[32 * 96];
    __shared__ float sb[96];
    int tid = threadIdx.x;
    for (int i = tid; i < 96 * 32; i += 128) {
        int out = i >> 5, k = i & 31;
        sWT[k * 96 + out] = Wi[i];
    }
    if (tid < 96) sb[tid] = bi[tid] + (tid < 64 ? bh[tid] : 0.0f);
    __syncthreads();
    int row = blockIdx.x * 128 + tid;
    if (row >= nrows) return;
    float h[32];
    const float4* xr = (const float4*)(x + (size_t)row * 32);
#pragma unroll
    for (int q = 0; q < 8; q++) {
        float4 v = xr[q];
        h[4 * q] = v.x; h[4 * q + 1] = v.y; h[4 * q + 2] = v.z; h[4 * q + 3] = v.w;
    }
    u64 acc[48];
    matvec96_col(h, sWT, acc);
    float4* t4 = (float4*)(g_table + (size_t)row * 96);
#pragma unroll
    for (int p = 0; p < 24; p++) {
        float2 a = u2f(acc[2 * p]);
        float2 b = u2f(acc[2 * p + 1]);
        t4[p] = make_float4(a.x + sb[4 * p], a.y + sb[4 * p + 1],
                            b.x + sb[4 * p + 2], b.y + sb[4 * p + 3]);
    }
}

// ---------------- GEMM-tiled fused scan ----------------
// Block: 128 paths x 96 outputs, 256 threads = 32(px) x 8(fy).
// Thread tile: 4 paths x (4 outs x 3 gates). Weights/h staged in shared as u64 pairs.
__global__ void __launch_bounds__(SCAN_THREADS) scan3_kernel(const float* __restrict__ Wh,
                                                             const float* __restrict__ bh)
{
    __shared__ __align__(16) u64 sww[32 * 48];        // [k][po], po-pair of outputs
    __shared__ __align__(16) u64 shh[32 * PSTR];      // [k][p], (h,h) duplicated
    __shared__ int sidx[TILE_P * L_N];
    __shared__ int slen[TILE_P];
    __shared__ float sbhn[32];

    int tid = threadIdx.x;
    int s0 = blockIdx.x * TILE_P;
    int pcount = min(TILE_P, P_N - s0);

    // stage weights as output-pairs: sww[k*48+po] = (Wh[2po][k], Wh[2po+1][k])
    for (int i = tid; i < 32 * 48; i += SCAN_THREADS) {
        int k = i / 48, po = i % 48;
        sww[k * 48 + po] = f2u(Wh[(2 * po) * 32 + k], Wh[(2 * po + 1) * 32 + k]);
    }
    if (tid < 32) sbhn[tid] = bh[64 + tid];
    // stage idx rows (2 int4 per path)
    for (int i = tid; i < pcount * 2; i += SCAN_THREADS)
        ((int4*)sidx)[i] = ((const int4*)(g_idx + (size_t)s0 * L_N))[i];
    if (tid < pcount) slen[tid] = g_len[s0 + tid];
    // zero pad rows for invalid paths
    if (pcount < TILE_P) {
        for (int i = tid; i < 32 * TILE_P; i += SCAN_THREADS) {
            int p = i & (TILE_P - 1);
            if (p >= pcount) shh[(i >> 7) * PSTR + p] = 0ull;
        }
    }
    // load h, duplicated
    for (int i = tid; i < pcount * 8; i += SCAN_THREADS) {
        int p = i >> 3, kq = i & 7;
        float4 v = ((const float4*)(g_p + (size_t)s0 * F_N))[i];
        shh[(4 * kq + 0) * PSTR + p] = f2u(v.x, v.x);
        shh[(4 * kq + 1) * PSTR + p] = f2u(v.y, v.y);
        shh[(4 * kq + 2) * PSTR + p] = f2u(v.z, v.z);
        shh[(4 * kq + 3) * PSTR + p] = f2u(v.w, v.w);
    }
    __syncthreads();

    int tmax = slen[0];      // descending sort: first slot has block max
    int px = tid >> 3;       // 0..31
    int fy = tid & 7;        // 0..7
    int pbase = px * 4;

    for (int t = 0; t <= tmax; t++) {
        u64 acc[6][4];
#pragma unroll
        for (int g = 0; g < 6; g++)
#pragma unroll
            for (int p = 0; p < 4; p++) acc[g][p] = 0ull;

#pragma unroll 4
        for (int k = 0; k < 32; k++) {
            const ulonglong2* wrow = (const ulonglong2*)(sww + k * 48);
            ulonglong2 wr = wrow[fy];
            ulonglong2 wz = wrow[8 + fy];
            ulonglong2 wn = wrow[16 + fy];
            const ulonglong2* hrow = (const ulonglong2*)(shh + k * PSTR + pbase);
            ulonglong2 h01 = hrow[0];
            ulonglong2 h23 = hrow[1];
            u64 hp[4] = {h01.x, h01.y, h23.x, h23.y};
#pragma unroll
            for (int p = 0; p < 4; p++) {
                acc[0][p] = ffma2(hp[p], wr.x, acc[0][p]);
                acc[1][p] = ffma2(hp[p], wr.y, acc[1][p]);
                acc[2][p] = ffma2(hp[p], wz.x, acc[2][p]);
                acc[3][p] = ffma2(hp[p], wz.y, acc[3][p]);
                acc[4][p] = ffma2(hp[p], wn.x, acc[4][p]);
                acc[5][p] = ffma2(hp[p], wn.y, acc[5][p]);
            }
        }
        __syncthreads();   // all k-loop reads of shh complete

#pragma unroll
        for (int p = 0; p < 4; p++) {
            int pp = pbase + p;
            if (pp < pcount && t <= slen[pp]) {
                int ch = sidx[pp * L_N + t];
                const u64* tgp = (const u64*)(g_table + (size_t)ch * 96);
#pragma unroll
                for (int q = 0; q < 2; q++) {
                    float2 gr = u2f(ldg64(tgp + 2 * fy + q));
                    float2 gz = u2f(ldg64(tgp + 16 + 2 * fy + q));
                    float2 gn = u2f(ldg64(tgp + 32 + 2 * fy + q));
                    float2 vr = u2f(acc[0 + q][p]);
                    float2 vz = u2f(acc[2 + q][p]);
                    float2 vn = u2f(acc[4 + q][p]);
#pragma unroll
                    for (int half = 0; half < 2; half++) {
                        int f = 4 * fy + 2 * q + half;
                        float ivr = half ? vr.y : vr.x;
                        float ivz = half ? vz.y : vz.x;
                        float ivn = half ? vn.y : vn.x;
                        float igr = half ? gr.y : gr.x;
                        float igz = half ? gz.y : gz.x;
                        float ign = half ? gn.y : gn.x;
                        float r = fast_sigmoid(igr + ivr);
                        float z = fast_sigmoid(igz + ivz);
                        float n = fast_tanh(ign + r * (ivn + sbhn[f]));
                        float hold = *((const float*)(shh + f * PSTR + pp));
                        float hnew = n + z * (hold - n);
                        shh[f * PSTR + pp] = f2u(hnew, hnew);
                    }
                }
            }
        }
        __syncthreads();   // epilogue writes visible before next k-loop
    }

    // tail: write back p and emit segment-sum contributions
    int p = tid & (TILE_P - 1);
    int kc = tid >> 7;     // 0 or 1 (half of the 32 features)
    if (p < pcount) {
        float v[16];
#pragma unroll
        for (int j = 0; j < 16; j++)
            v[j] = *((const float*)(shh + (kc * 16 + j) * PSTR + p));
        float4* dst = (float4*)(g_p + (size_t)(s0 + p) * F_N + kc * 16);
#pragma unroll
        for (int q = 0; q < 4; q++)
            dst[q] = make_float4(v[4 * q], v[4 * q + 1], v[4 * q + 2], v[4 * q + 3]);
        int ln = slen[p];
#pragma unroll 1
        for (int t = 0; t <= ln; t++) {
            int ch = sidx[p * L_N + t];
            float* base = g_agg + (size_t)ch * F_N + kc * 16;
            red_add_v4(base + 0,  make_float4(v[0],  v[1],  v[2],  v[3]));
            red_add_v4(base + 4,  make_float4(v[4],  v[5],  v[6],  v[7]));
            red_add_v4(base + 8,  make_float4(v[8],  v[9],  v[10], v[11]));
            red_add_v4(base + 12, make_float4(v[12], v[13], v[14], v[15]));
        }
    }
}

// ---------------- per-step: channel GRU (gi from table on agg) ----------------
__global__ void __launch_bounds__(128) gru2_kernel(float* __restrict__ c,
                                                   const float* __restrict__ Wh,
                                                   const float* __restrict__ bh)
{
    __shared__ __align__(16) float sWT[32 * 96];
    __shared__ float sbhn[32];
    int tid = threadIdx.x;
    for (int i = tid; i < 96 * 32; i += 128) {
        int out = i >> 5, k = i & 31;
        sWT[k * 96 + out] = Wh[i];
    }
    if (tid < 32) sbhn[tid] = bh[64 + tid];
    __syncthreads();
    int ch = blockIdx.x * 128 + tid;
    if (ch >= C_N) return;
    float h[32];
    {
        const float4* cp = (const float4*)(c + (size_t)ch * F_N);
#pragma unroll
        for (int q = 0; q < 8; q++) {
            float4 v = cp[q];
            h[4 * q] = v.x; h[4 * q + 1] = v.y; h[4 * q + 2] = v.z; h[4 * q + 3] = v.w;
        }
    }
    const float4* tg = (const float4*)(g_table + (size_t)ch * 96);
    u64 acc[48];
    matvec96_col(h, sWT, acc);
    gru_epilogue(h, tg, acc, sbhn);
    float4* cp = (float4*)(c + (size_t)ch * F_N);
#pragma unroll
    for (int q = 0; q < 8; q++)
        cp[q] = make_float4(h[4 * q], h[4 * q + 1], h[4 * q + 2], h[4 * q + 3]);
}

// ---------------- final scatter of p to original order ----------------
__global__ void __launch_bounds__(128) scatterp_kernel(float* __restrict__ outp) {
    int s = blockIdx.x * 128 + threadIdx.x;
    if (s >= P_N) return;
    int path = g_order[s];
    const float4* src = (const float4*)(g_p + (size_t)s * F_N);
    float4* dst = (float4*)(outp + (size_t)path * F_N);
#pragma unroll
    for (int q = 0; q < 8; q++) dst[q] = src[q];
}

// ---------------- launch ----------------
extern "C" void kernel_launch(void* const* d_in, const int* in_sizes, int n_in,
                              void* d_out, int out_size)
{
    const float* path_raw    = (const float*)d_in[0];
    const float* channel_raw = (const float*)d_in[1];
    const int*   pci         = (const int*)d_in[2];
    const int*   plen        = (const int*)d_in[3];
    // d_in[4] = num_steps (constant 5)
    const float* Wp  = (const float*)d_in[5];
    const float* bp  = (const float*)d_in[6];
    const float* Wc  = (const float*)d_in[7];
    const float* bc  = (const float*)d_in[8];
    const float* Wi1 = (const float*)d_in[9];
    const float* Wh1 = (const float*)d_in[10];
    const float* bi1 = (const float*)d_in[11];
    const float* bh1 = (const float*)d_in[12];
    const float* Wi2 = (const float*)d_in[13];
    const float* Wh2 = (const float*)d_in[14];
    const float* bi2 = (const float*)d_in[15];
    const float* bh2 = (const float*)d_in[16];

    float* outp = (float*)d_out;
    float* c    = outp + (size_t)P_N * F_N;

    void* aggPtr = nullptr;
    cudaGetSymbolAddress(&aggPtr, g_agg);
    float* aggF = (float*)aggPtr;

    int gridP128 = (P_N + 127) / 128;
    int gridC    = (C_N + 127) / 128;
    int gridScan = (P_N + TILE_P - 1) / TILE_P;

    zero_cnt_kernel<<<1, 32>>>();
    hist_kernel<<<gridP128, 128>>>(plen);
    prefix_kernel<<<1, 32>>>();
    scatter_kernel<<<gridP128, 128>>>(plen);
    build_kernel<<<gridP128, 128>>>(plen, pci, path_raw, Wp, bp);
    initc_kernel<<<gridC, 128>>>(channel_raw, Wc, bc, c);

    for (int st = 0; st < NSTEPS; st++) {
        cudaMemsetAsync(aggPtr, 0, sizeof(float) * (size_t)C_N * F_N, 0);
        gi_kernel<<<gridC, 128>>>(c, C_N, Wi1, bi1, bh1);
        scan3_kernel<<<gridScan, SCAN_THREADS>>>(Wh1, bh1);
        gi_kernel<<<gridC, 128>>>(aggF, C_N, Wi2, bi2, bh2);
        gru2_kernel<<<gridC, 128>>>(c, Wh2, bh2);
    }
    scatterp_kernel<<<gridP128, 128>>>(outp);
}

// round 4
// speedup vs baseline: 1.5317x; 1.1077x over previous
#include <cuda_runtime.h>

#define P_N 200000
#define C_N 50000
#define L_N 8
#define F_N 32
#define DIN 64
#define NSTEPS 5

#define TILE_P 128
#define SCAN_THREADS 256
#define PSTR 130   // u64 stride of staged rows

#define GRID_P128 ((P_N + 127) / 128)
#define GRID_C128 ((C_N + 127) / 128)

typedef unsigned long long u64;

// ---------------- device scratch ----------------
__device__ float g_p[(size_t)P_N * F_N];
__device__ int   g_order[P_N];
__device__ int   g_idx[(size_t)P_N * L_N];
__device__ int   g_len[P_N];
__device__ float g_agg[(size_t)C_N * F_N];
__device__ float g_table[(size_t)C_N * 96];
__device__ int   g_cnt[16];
__device__ int   g_blkhist[GRID_P128 * 8];

// ---------------- helpers ----------------
__device__ __forceinline__ u64 ffma2(u64 a, u64 b, u64 c) {
    u64 d;
    asm("fma.rn.f32x2 %0, %1, %2, %3;" : "=l"(d) : "l"(a), "l"(b), "l"(c));
    return d;
}
__device__ __forceinline__ float2 u2f(u64 v) {
    float2 r;
    asm("mov.b64 {%0,%1}, %2;" : "=f"(r.x), "=f"(r.y) : "l"(v));
    return r;
}
__device__ __forceinline__ u64 f2u(float a, float b) {
    u64 r;
    asm("mov.b64 %0, {%1,%2};" : "=l"(r) : "f"(a), "f"(b));
    return r;
}
__device__ __forceinline__ float hsum(u64 v) { float2 f = u2f(v); return f.x + f.y; }

__device__ __forceinline__ float tanh_ap(float x) {
    float y;
    asm("tanh.approx.f32 %0, %1;" : "=f"(y) : "f"(x));
    return y;
}
__device__ __forceinline__ float fast_sigmoid(float v) {
    return fmaf(0.5f, tanh_ap(0.5f * v), 0.5f);
}
__device__ __forceinline__ float fast_tanh(float v) { return tanh_ap(v); }

__device__ __forceinline__ void red_add_v4(float* p, float4 v) {
    asm volatile("red.global.add.v4.f32 [%0], {%1,%2,%3,%4};"
                 :: "l"(p), "f"(v.x), "f"(v.y), "f"(v.z), "f"(v.w) : "memory");
}
__device__ __forceinline__ u64 ldg64(const u64* p) {
    u64 v;
    asm("ld.global.nc.b64 %0, [%1];" : "=l"(v) : "l"(p));
    return v;
}

// ---------------- sorting (counting sort, DESCENDING length, no zero kernel) ----------------
__global__ void hist_kernel(const int* __restrict__ plen) {
    __shared__ int lh[8];
    int tid = threadIdx.x;
    if (tid < 8) lh[tid] = 0;
    __syncthreads();
    int i = blockIdx.x * 128 + tid;
    if (i < P_N) {
        int b = plen[i]; b = b < 0 ? 0 : (b > 7 ? 7 : b);
        atomicAdd(&lh[b], 1);
    }
    __syncthreads();
    if (tid < 8) g_blkhist[blockIdx.x * 8 + tid] = lh[tid];
}

__global__ void prefix_kernel() {
    __shared__ int tot[8];
    int tid = threadIdx.x;
    if (tid < 8) tot[tid] = 0;
    __syncthreads();
    int local[8] = {0, 0, 0, 0, 0, 0, 0, 0};
    for (int j = tid; j < GRID_P128; j += 256) {
#pragma unroll
        for (int b = 0; b < 8; b++) local[b] += g_blkhist[j * 8 + b];
    }
#pragma unroll
    for (int b = 0; b < 8; b++) atomicAdd(&tot[b], local[b]);
    __syncthreads();
    if (tid == 0) {
        int acc = 0;
#pragma unroll
        for (int b = 7; b >= 0; b--) { int cv = tot[b]; g_cnt[b] = acc; acc += cv; }
    }
}

__global__ void scatter_kernel(const int* __restrict__ plen) {
    int i = blockIdx.x * blockDim.x + threadIdx.x;
    if (i < P_N) {
        int b = plen[i]; b = b < 0 ? 0 : (b > 7 ? 7 : b);
        int pos = atomicAdd(&g_cnt[b], 1);
        g_order[pos] = i;
    }
}

// ---------------- fused build (paths) + initc (channels) ----------------
__global__ void __launch_bounds__(128) buildinit_kernel(const int* __restrict__ plen,
                                                        const int* __restrict__ pci,
                                                        const float* __restrict__ praw,
                                                        const float* __restrict__ craw,
                                                        const float* __restrict__ Wp,
                                                        const float* __restrict__ bp,
                                                        const float* __restrict__ Wc,
                                                        const float* __restrict__ bc,
                                                        float* __restrict__ c)
{
    __shared__ __align__(16) float sWt[F_N * DIN];
    __shared__ float sb[F_N];
    int tid = threadIdx.x;
    bool isPath = blockIdx.x < GRID_P128;
    const float* W = isPath ? Wp : Wc;
    const float* b = isPath ? bp : bc;
    for (int i = tid; i < DIN * F_N; i += 128) {
        int d = i >> 5, f = i & 31;
        sWt[f * DIN + d] = W[i];
    }
    if (tid < F_N) sb[tid] = b[tid];
    __syncthreads();

    int row, srcrow;
    const float* xsrc;
    float* dst;
    if (isPath) {
        row = blockIdx.x * 128 + tid;
        if (row >= P_N) return;
        srcrow = g_order[row];
        g_len[row] = plen[srcrow];
        const int4* si = (const int4*)(pci + (size_t)srcrow * L_N);
        int4* di = (int4*)(g_idx + (size_t)row * L_N);
        di[0] = si[0]; di[1] = si[1];
        xsrc = praw;
        dst = g_p + (size_t)row * F_N;
    } else {
        row = (blockIdx.x - GRID_P128) * 128 + tid;
        if (row >= C_N) return;
        srcrow = row;
        xsrc = craw;
        dst = c + (size_t)row * F_N;
    }

    u64 x2[32];
    const ulonglong2* xg = (const ulonglong2*)(xsrc + (size_t)srcrow * DIN);
#pragma unroll
    for (int q = 0; q < 16; q++) { ulonglong2 v = xg[q]; x2[2 * q] = v.x; x2[2 * q + 1] = v.y; }
    const u64* wt = (const u64*)sWt;
    float4* out4 = (float4*)dst;
    for (int f0 = 0; f0 < F_N; f0 += 4) {
        u64 a0 = 0, a1 = 0, a2 = 0, a3 = 0;
        const u64* w0 = wt + (f0 + 0) * 32;
        const u64* w1 = wt + (f0 + 1) * 32;
        const u64* w2 = wt + (f0 + 2) * 32;
        const u64* w3 = wt + (f0 + 3) * 32;
#pragma unroll
        for (int k = 0; k < 32; k++) {
            a0 = ffma2(x2[k], w0[k], a0);
            a1 = ffma2(x2[k], w1[k], a1);
            a2 = ffma2(x2[k], w2[k], a2);
            a3 = ffma2(x2[k], w3[k], a3);
        }
        float4 r;
        r.x = fmaxf(hsum(a0) + sb[f0 + 0], 0.0f);
        r.y = fmaxf(hsum(a1) + sb[f0 + 1], 0.0f);
        r.z = fmaxf(hsum(a2) + sb[f0 + 2], 0.0f);
        r.w = fmaxf(hsum(a3) + sb[f0 + 3], 0.0f);
        out4[f0 >> 2] = r;
    }
}

// ---------------- tiled gi: g_table[row] = x[row]@Wi^T + bi (+bh for r,z) ----------------
// Block: 128 rows x 96 outs, 256 threads = 32(px) x 8(fy); thread tile 4 rows x 12 outs.
__global__ void __launch_bounds__(256) gi_tiled(const float* __restrict__ x,
                                                const float* __restrict__ Wi,
                                                const float* __restrict__ bi,
                                                const float* __restrict__ bh,
                                                int zero_agg)
{
    __shared__ __align__(16) u64 sww[32 * 48];
    __shared__ __align__(16) u64 sxx[32 * PSTR];
    __shared__ float sb[96];

    int tid = threadIdx.x;
    int s0 = blockIdx.x * 128;
    int rcount = min(128, C_N - s0);

    for (int i = tid; i < 32 * 48; i += 256) {
        int k = i / 48, po = i % 48;
        sww[k * 48 + po] = f2u(Wi[(2 * po) * 32 + k], Wi[(2 * po + 1) * 32 + k]);
    }
    if (tid < 96) sb[tid] = bi[tid] + (tid < 64 ? bh[tid] : 0.0f);

    if (zero_agg) {
        float4 z4 = make_float4(0.f, 0.f, 0.f, 0.f);
        for (int i = blockIdx.x * 256 + tid; i < C_N * F_N / 4; i += gridDim.x * 256)
            ((float4*)g_agg)[i] = z4;
    }
    if (rcount < 128) {
        for (int i = tid; i < 32 * 128; i += 256) {
            int p = i & 127;
            if (p >= rcount) sxx[(i >> 7) * PSTR + p] = 0ull;
        }
    }
    for (int i = tid; i < rcount * 8; i += 256) {
        int p = i >> 3, kq = i & 7;
        float4 v = ((const float4*)(x + (size_t)s0 * F_N))[i];
        sxx[(4 * kq + 0) * PSTR + p] = f2u(v.x, v.x);
        sxx[(4 * kq + 1) * PSTR + p] = f2u(v.y, v.y);
        sxx[(4 * kq + 2) * PSTR + p] = f2u(v.z, v.z);
        sxx[(4 * kq + 3) * PSTR + p] = f2u(v.w, v.w);
    }
    __syncthreads();

    int px = tid >> 3, fy = tid & 7;
    int pbase = px * 4;
    u64 acc[6][4];
#pragma unroll
    for (int g = 0; g < 6; g++)
#pragma unroll
        for (int p = 0; p < 4; p++) acc[g][p] = 0ull;

#pragma unroll 4
    for (int k = 0; k < 32; k++) {
        const ulonglong2* wrow = (const ulonglong2*)(sww + k * 48);
        ulonglong2 wr = wrow[fy];
        ulonglong2 wz = wrow[8 + fy];
        ulonglong2 wn = wrow[16 + fy];
        const ulonglong2* xrow = (const ulonglong2*)(sxx + k * PSTR + pbase);
        ulonglong2 x01 = xrow[0];
        ulonglong2 x23 = xrow[1];
        u64 xp[4] = {x01.x, x01.y, x23.x, x23.y};
#pragma unroll
        for (int p = 0; p < 4; p++) {
            acc[0][p] = ffma2(xp[p], wr.x, acc[0][p]);
            acc[1][p] = ffma2(xp[p], wr.y, acc[1][p]);
            acc[2][p] = ffma2(xp[p], wz.x, acc[2][p]);
            acc[3][p] = ffma2(xp[p], wz.y, acc[3][p]);
            acc[4][p] = ffma2(xp[p], wn.x, acc[4][p]);
            acc[5][p] = ffma2(xp[p], wn.y, acc[5][p]);
        }
    }

#pragma unroll
    for (int p = 0; p < 4; p++) {
        int pp = pbase + p;
        if (pp < rcount) {
            u64* dst = (u64*)(g_table + (size_t)(s0 + pp) * 96);
#pragma unroll
            for (int gate = 0; gate < 3; gate++) {
#pragma unroll
                for (int q = 0; q < 2; q++) {
                    int fbase = 4 * fy + 2 * q;
                    float2 a = u2f(acc[2 * gate + q][p]);
                    dst[gate * 16 + 2 * fy + q] =
                        f2u(a.x + sb[gate * 32 + fbase], a.y + sb[gate * 32 + fbase + 1]);
                }
            }
        }
    }
}

// ---------------- GEMM-tiled fused scan ----------------
__global__ void __launch_bounds__(SCAN_THREADS) scan3_kernel(const float* __restrict__ Wh,
                                                             const float* __restrict__ bh)
{
    __shared__ __align__(16) u64 sww[32 * 48];
    __shared__ __align__(16) u64 shh[32 * PSTR];
    __shared__ int sidx[TILE_P * L_N];
    __shared__ int slen[TILE_P];
    __shared__ float sbhn[32];

    int tid = threadIdx.x;
    int s0 = blockIdx.x * TILE_P;
    int pcount = min(TILE_P, P_N - s0);

    for (int i = tid; i < 32 * 48; i += SCAN_THREADS) {
        int k = i / 48, po = i % 48;
        sww[k * 48 + po] = f2u(Wh[(2 * po) * 32 + k], Wh[(2 * po + 1) * 32 + k]);
    }
    if (tid < 32) sbhn[tid] = bh[64 + tid];
    for (int i = tid; i < pcount * 2; i += SCAN_THREADS)
        ((int4*)sidx)[i] = ((const int4*)(g_idx + (size_t)s0 * L_N))[i];
    if (tid < pcount) slen[tid] = g_len[s0 + tid];
    if (pcount < TILE_P) {
        for (int i = tid; i < 32 * TILE_P; i += SCAN_THREADS) {
            int p = i & (TILE_P - 1);
            if (p >= pcount) shh[(i >> 7) * PSTR + p] = 0ull;
        }
    }
    for (int i = tid; i < pcount * 8; i += SCAN_THREADS) {
        int p = i >> 3, kq = i & 7;
        float4 v = ((const float4*)(g_p + (size_t)s0 * F_N))[i];
        shh[(4 * kq + 0) * PSTR + p] = f2u(v.x, v.x);
        shh[(4 * kq + 1) * PSTR + p] = f2u(v.y, v.y);
        shh[(4 * kq + 2) * PSTR + p] = f2u(v.z, v.z);
        shh[(4 * kq + 3) * PSTR + p] = f2u(v.w, v.w);
    }
    __syncthreads();

    int tmax = slen[0];
    int px = tid >> 3;
    int fy = tid & 7;
    int pbase = px * 4;

    for (int t = 0; t <= tmax; t++) {
        u64 acc[6][4];
#pragma unroll
        for (int g = 0; g < 6; g++)
#pragma unroll
            for (int p = 0; p < 4; p++) acc[g][p] = 0ull;

#pragma unroll 4
        for (int k = 0; k < 32; k++) {
            const ulonglong2* wrow = (const ulonglong2*)(sww + k * 48);
            ulonglong2 wr = wrow[fy];
            ulonglong2 wz = wrow[8 + fy];
            ulonglong2 wn = wrow[16 + fy];
            const ulonglong2* hrow = (const ulonglong2*)(shh + k * PSTR + pbase);
            ulonglong2 h01 = hrow[0];
            ulonglong2 h23 = hrow[1];
            u64 hp[4] = {h01.x, h01.y, h23.x, h23.y};
#pragma unroll
            for (int p = 0; p < 4; p++) {
                acc[0][p] = ffma2(hp[p], wr.x, acc[0][p]);
                acc[1][p] = ffma2(hp[p], wr.y, acc[1][p]);
                acc[2][p] = ffma2(hp[p], wz.x, acc[2][p]);
                acc[3][p] = ffma2(hp[p], wz.y, acc[3][p]);
                acc[4][p] = ffma2(hp[p], wn.x, acc[4][p]);
                acc[5][p] = ffma2(hp[p], wn.y, acc[5][p]);
            }
        }
        __syncthreads();

#pragma unroll
        for (int p = 0; p < 4; p++) {
            int pp = pbase + p;
            if (pp < pcount && t <= slen[pp]) {
                int ch = sidx[pp * L_N + t];
                const u64* tgp = (const u64*)(g_table + (size_t)ch * 96);
#pragma unroll
                for (int q = 0; q < 2; q++) {
                    float2 gr = u2f(ldg64(tgp + 2 * fy + q));
                    float2 gz = u2f(ldg64(tgp + 16 + 2 * fy + q));
                    float2 gn = u2f(ldg64(tgp + 32 + 2 * fy + q));
                    float2 vr = u2f(acc[0 + q][p]);
                    float2 vz = u2f(acc[2 + q][p]);
                    float2 vn = u2f(acc[4 + q][p]);
#pragma unroll
                    for (int half = 0; half < 2; half++) {
                        int f = 4 * fy + 2 * q + half;
                        float ivr = half ? vr.y : vr.x;
                        float ivz = half ? vz.y : vz.x;
                        float ivn = half ? vn.y : vn.x;
                        float igr = half ? gr.y : gr.x;
                        float igz = half ? gz.y : gz.x;
                        float ign = half ? gn.y : gn.x;
                        float r = fast_sigmoid(igr + ivr);
                        float z = fast_sigmoid(igz + ivz);
                        float n = fast_tanh(ign + r * (ivn + sbhn[f]));
                        float hold = *((const float*)(shh + f * PSTR + pp));
                        float hnew = n + z * (hold - n);
                        shh[f * PSTR + pp] = f2u(hnew, hnew);
                    }
                }
            }
        }
        __syncthreads();
    }

    int p = tid & (TILE_P - 1);
    int kc = tid >> 7;
    if (p < pcount) {
        float v[16];
#pragma unroll
        for (int j = 0; j < 16; j++)
            v[j] = *((const float*)(shh + (kc * 16 + j) * PSTR + p));
        float4* dst = (float4*)(g_p + (size_t)(s0 + p) * F_N + kc * 16);
#pragma unroll
        for (int q = 0; q < 4; q++)
            dst[q] = make_float4(v[4 * q], v[4 * q + 1], v[4 * q + 2], v[4 * q + 3]);
        int ln = slen[p];
#pragma unroll 1
        for (int t = 0; t <= ln; t++) {
            int ch = sidx[p * L_N + t];
            float* base = g_agg + (size_t)ch * F_N + kc * 16;
            red_add_v4(base + 0,  make_float4(v[0],  v[1],  v[2],  v[3]));
            red_add_v4(base + 4,  make_float4(v[4],  v[5],  v[6],  v[7]));
            red_add_v4(base + 8,  make_float4(v[8],  v[9],  v[10], v[11]));
            red_add_v4(base + 12, make_float4(v[12], v[13], v[14], v[15]));
        }
    }
}

// ---------------- tiled channel GRU: c = GRU(table-row(agg), c) ----------------
__global__ void __launch_bounds__(256) gru2_tiled(float* __restrict__ c,
                                                  const float* __restrict__ Wh,
                                                  const float* __restrict__ bh)
{
    __shared__ __align__(16) u64 sww[32 * 48];
    __shared__ __align__(16) u64 shh[32 * PSTR];
    __shared__ float sbhn[32];

    int tid = threadIdx.x;
    int s0 = blockIdx.x * 128;
    int rcount = min(128, C_N - s0);

    for (int i = tid; i < 32 * 48; i += 256) {
        int k = i / 48, po = i % 48;
        sww[k * 48 + po] = f2u(Wh[(2 * po) * 32 + k], Wh[(2 * po + 1) * 32 + k]);
    }
    if (tid < 32) sbhn[tid] = bh[64 + tid];
    if (rcount < 128) {
        for (int i = tid; i < 32 * 128; i += 256) {
            int p = i & 127;
            if (p >= rcount) shh[(i >> 7) * PSTR + p] = 0ull;
        }
    }
    for (int i = tid; i < rcount * 8; i += 256) {
        int p = i >> 3, kq = i & 7;
        float4 v = ((const float4*)(c + (size_t)s0 * F_N))[i];
        shh[(4 * kq + 0) * PSTR + p] = f2u(v.x, v.x);
        shh[(4 * kq + 1) * PSTR + p] = f2u(v.y, v.y);
        shh[(4 * kq + 2) * PSTR + p] = f2u(v.z, v.z);
        shh[(4 * kq + 3) * PSTR + p] = f2u(v.w, v.w);
    }
    __syncthreads();

    int px = tid >> 3, fy = tid & 7;
    int pbase = px * 4;
    u64 acc[6][4];
#pragma unroll
    for (int g = 0; g < 6; g++)
#pragma unroll
        for (int p = 0; p < 4; p++) acc[g][p] = 0ull;

#pragma unroll 4
    for (int k = 0; k < 32; k++) {
        const ulonglong2* wrow = (const ulonglong2*)(sww + k * 48);
        ulonglong2 wr = wrow[fy];
        ulonglong2 wz = wrow[8 + fy];
        ulonglong2 wn = wrow[16 + fy];
        const ulonglong2* hrow = (const ulonglong2*)(shh + k * PSTR + pbase);
        ulonglong2 h01 = hrow[0];
        ulonglong2 h23 = hrow[1];
        u64 hp[4] = {h01.x, h01.y, h23.x, h23.y};
#pragma unroll
        for (int p = 0; p < 4; p++) {
            acc[0][p] = ffma2(hp[p], wr.x, acc[0][p]);
            acc[1][p] = ffma2(hp[p], wr.y, acc[1][p]);
            acc[2][p] = ffma2(hp[p], wz.x, acc[2][p]);
            acc[3][p] = ffma2(hp[p], wz.y, acc[3][p]);
            acc[4][p] = ffma2(hp[p], wn.x, acc[4][p]);
            acc[5][p] = ffma2(hp[p], wn.y, acc[5][p]);
        }
    }

#pragma unroll
    for (int p = 0; p < 4; p++) {
        int pp = pbase + p;
        if (pp < rcount) {
            int ch = s0 + pp;
            const u64* tgp = (const u64*)(g_table + (size_t)ch * 96);
            u64* cdst = (u64*)(c + (size_t)ch * F_N);
#pragma unroll
            for (int q = 0; q < 2; q++) {
                float2 gr = u2f(ldg64(tgp + 2 * fy + q));
                float2 gz = u2f(ldg64(tgp + 16 + 2 * fy + q));
                float2 gn = u2f(ldg64(tgp + 32 + 2 * fy + q));
                float2 vr = u2f(acc[0 + q][p]);
                float2 vz = u2f(acc[2 + q][p]);
                float2 vn = u2f(acc[4 + q][p]);
                float hnew2[2];
#pragma unroll
                for (int half = 0; half < 2; half++) {
                    int f = 4 * fy + 2 * q + half;
                    float ivr = half ? vr.y : vr.x;
                    float ivz = half ? vz.y : vz.x;
                    float ivn = half ? vn.y : vn.x;
                    float igr = half ? gr.y : gr.x;
                    float igz = half ? gz.y : gz.x;
                    float ign = half ? gn.y : gn.x;
                    float r = fast_sigmoid(igr + ivr);
                    float z = fast_sigmoid(igz + ivz);
                    float n = fast_tanh(ign + r * (ivn + sbhn[f]));
                    float hold = *((const float*)(shh + f * PSTR + pp));
                    hnew2[half] = n + z * (hold - n);
                }
                cdst[2 * fy + q] = f2u(hnew2[0], hnew2[1]);
            }
        }
    }
}

// ---------------- final scatter of p to original order ----------------
__global__ void __launch_bounds__(128) scatterp_kernel(float* __restrict__ outp) {
    int s = blockIdx.x * 128 + threadIdx.x;
    if (s >= P_N) return;
    int path = g_order[s];
    const float4* src = (const float4*)(g_p + (size_t)s * F_N);
    float4* dst = (float4*)(outp + (size_t)path * F_N);
#pragma unroll
    for (int q = 0; q < 8; q++) dst[q] = src[q];
}

// ---------------- launch ----------------
extern "C" void kernel_launch(void* const* d_in, const int* in_sizes, int n_in,
                              void* d_out, int out_size)
{
    const float* path_raw    = (const float*)d_in[0];
    const float* channel_raw = (const float*)d_in[1];
    const int*   pci         = (const int*)d_in[2];
    const int*   plen        = (const int*)d_in[3];
    // d_in[4] = num_steps (constant 5)
    const float* Wp  = (const float*)d_in[5];
    const float* bp  = (const float*)d_in[6];
    const float* Wc  = (const float*)d_in[7];
    const float* bc  = (const float*)d_in[8];
    const float* Wi1 = (const float*)d_in[9];
    const float* Wh1 = (const float*)d_in[10];
    const float* bi1 = (const float*)d_in[11];
    const float* bh1 = (const float*)d_in[12];
    const float* Wi2 = (const float*)d_in[13];
    const float* Wh2 = (const float*)d_in[14];
    const float* bi2 = (const float*)d_in[15];
    const float* bh2 = (const float*)d_in[16];

    float* outp = (float*)d_out;
    float* c    = outp + (size_t)P_N * F_N;

    void* aggPtr = nullptr;
    cudaGetSymbolAddress(&aggPtr, g_agg);
    float* aggF = (float*)aggPtr;

    int gridScan = (P_N + TILE_P - 1) / TILE_P;

    hist_kernel<<<GRID_P128, 128>>>(plen);
    prefix_kernel<<<1, 256>>>();
    scatter_kernel<<<GRID_P128, 128>>>(plen);
    buildinit_kernel<<<GRID_P128 + GRID_C128, 128>>>(plen, pci, path_raw, channel_raw,
                                                     Wp, bp, Wc, bc, c);

    for (int st = 0; st < NSTEPS; st++) {
        gi_tiled<<<GRID_C128, 256>>>(c, Wi1, bi1, bh1, 1);      // also zeros g_agg
        scan3_kernel<<<gridScan, SCAN_THREADS>>>(Wh1, bh1);     // launch #6 on step 0
        gi_tiled<<<GRID_C128, 256>>>(aggF, Wi2, bi2, bh2, 0);
        gru2_tiled<<<GRID_C128, 256>>>(c, Wh2, bh2);
    }
    scatterp_kernel<<<GRID_P128, 128>>>(outp);
}